// round 15
// baseline (speedup 1.0000x reference)
#include <cuda_runtime.h>
#include <cuda_fp16.h>
#include <math.h>
#include <stdint.h>

#define B_   2
#define H_   8
#define NQ_  2048
#define NK_  2048
#define DM_  512
#define HD_  64
#define EXP2C 0.18033688011112042f   /* 0.125 * log2(e) */

#define SH2 36   // half2 words per 64-half row; 36%32==4 -> conflict-free frags
#define XF  40   // f32 words per 32-f32 row; conflict-free float2 frags
#define WS  20   // uint32 words per 32-half W row
#define MS  68   // f32 words per 64-f32 mask row; 68%32==4 -> <=2-way on float2

// Scratch (allocation-free rule: __device__ globals)
__device__ __half g_Q[B_*H_*NQ_*HD_];
__device__ __half g_K[B_*H_*NK_*HD_];
__device__ __half g_V[B_*H_*NK_*HD_];
__device__ __half g_Wh[3*DM_*DM_];
__device__ float  g_diag[B_*H_*NK_];

// ---------------------------------------------------------------------------
// helpers
// ---------------------------------------------------------------------------
__device__ __forceinline__ float fast_ex2(float x) {
    float y;
    asm("ex2.approx.ftz.f32 %0, %1;" : "=f"(y) : "f"(x));
    return y;
}
__device__ __forceinline__ uint32_t f2h2(float lo, float hi) {
    __half2 h = __floats2half2_rn(lo, hi);
    return *reinterpret_cast<uint32_t*>(&h);
}
__device__ __forceinline__ uint32_t ldsf2h(const float* p) {
    float2 v = *(const float2*)p;
    return f2h2(v.x, v.y);
}
__device__ __forceinline__ void mma_f16(float c[4], const uint32_t a[4],
                                        uint32_t b0, uint32_t b1) {
    asm volatile(
        "mma.sync.aligned.m16n8k16.row.col.f32.f16.f16.f32 "
        "{%0,%1,%2,%3}, {%4,%5,%6,%7}, {%8,%9}, {%0,%1,%2,%3};\n"
        : "+f"(c[0]), "+f"(c[1]), "+f"(c[2]), "+f"(c[3])
        : "r"(a[0]), "r"(a[1]), "r"(a[2]), "r"(a[3]), "r"(b0), "r"(b1));
}
__device__ __forceinline__ void ldsm_x4_t(uint32_t r[4], uint32_t addr) {
    asm volatile(
        "ldmatrix.sync.aligned.m8n8.x4.trans.shared.b16 {%0,%1,%2,%3}, [%4];"
        : "=r"(r[0]), "=r"(r[1]), "=r"(r[2]), "=r"(r[3]) : "r"(addr));
}
__device__ __forceinline__ void ldsm_x4(uint32_t r[4], uint32_t addr) {
    asm volatile(
        "ldmatrix.sync.aligned.m8n8.x4.shared.b16 {%0,%1,%2,%3}, [%4];"
        : "=r"(r[0]), "=r"(r[1]), "=r"(r[2]), "=r"(r[3]) : "r"(addr));
}
__device__ __forceinline__ uint32_t smem_u32(const void* p) {
    uint32_t a;
    asm("{ .reg .u64 t; cvta.to.shared.u64 t, %1; cvt.u32.u64 %0, t; }"
        : "=r"(a) : "l"(p));
    return a;
}
#define CPASYNC16(dst, src) \
    asm volatile("cp.async.cg.shared.global [%0], [%1], 16;" :: "r"(dst), "l"(src))
#define CPCOMMIT()  asm volatile("cp.async.commit_group;" ::: "memory")
#define CPWAIT0()   asm volatile("cp.async.wait_group 0;"  ::: "memory")
#define CPWAIT1()   asm volatile("cp.async.wait_group 1;"  ::: "memory")

// ---------------------------------------------------------------------------
// W fp32 -> fp16 pre-convert. Wq additionally scaled by EXP2C so attention
// scores come out pre-scaled in log2 domain (kills 32 FMUL/thread/tile).
// ---------------------------------------------------------------------------
__global__ void wcvt_kernel(const float* __restrict__ Wq,
                            const float* __restrict__ Wk,
                            const float* __restrict__ Wv)
{
    int idx = blockIdx.x * 256 + threadIdx.x;        // 0 .. 196607 (float4)
    const float* src = (idx < 65536) ? Wq : (idx < 131072 ? Wk : Wv);
    float s = (idx < 65536) ? EXP2C : 1.0f;
    float4 w = *(const float4*)(src + (size_t)(idx & 65535) * 4);
    uint2 o;
    o.x = f2h2(w.x * s, w.y * s);
    o.y = f2h2(w.z * s, w.w * s);
    *(uint2*)(g_Wh + (size_t)idx * 4) = o;
}

// ---------------------------------------------------------------------------
// Projection: fp16 m16n8k16, cp.async double-buffered, 512 threads.
// Bias for the Q projection scaled by EXP2C to match scaled Wq.
// ---------------------------------------------------------------------------
#define PROJ_SMEM (15360 * 4)

__global__ __launch_bounds__(512) void proj_kernel(
    const float* __restrict__ q, const float* __restrict__ k,
    const float* __restrict__ v,
    const float* __restrict__ bq, const float* __restrict__ bk,
    const float* __restrict__ bv)
{
    extern __shared__ float smf[];
    uint32_t* smu = (uint32_t*)smf;
    const uint32_t sb = smem_u32(smf);

    const float *X, *bias;
    const __half* Wh;
    __half* outp;
    float bscl = 1.0f;
    if (blockIdx.z == 0)      { X = q; bias = bq; Wh = g_Wh;              outp = g_Q; bscl = EXP2C; }
    else if (blockIdx.z == 1) { X = k; bias = bk; Wh = g_Wh + DM_*DM_;    outp = g_K; }
    else                      { X = v; bias = bv; Wh = g_Wh + 2*DM_*DM_;  outp = g_V; }

    const int tid  = threadIdx.x;
    const int lane = tid & 31, warp = tid >> 5;
    const int lq = lane >> 2, lr = lane & 3;
    const int m0 = (warp & 7) * 16;
    const int n0 = (warp >> 3) * 64;
    const int row0 = blockIdx.y * 128;
    const int col0 = blockIdx.x * 128;

    const int sr = tid >> 3;
    const int sc = (tid & 7) << 2;
    const int wr = tid >> 2;
    const int wg = (tid & 3) << 3;

    float acc[8][4];
    #pragma unroll
    for (int j = 0; j < 8; j++)
        #pragma unroll
        for (int i = 0; i < 4; i++) acc[j][i] = 0.f;

    {
        #pragma unroll
        for (int it = 0; it < 2; it++) {
            int r = sr + it*64;
            CPASYNC16(sb + (uint32_t)((r*XF + sc) * 4),
                      X + (size_t)(row0 + r) * DM_ + sc);
        }
        CPASYNC16(sb + (uint32_t)((10240 + wr*WS) * 4 + wg*2),
                  Wh + (size_t)(col0 + wr) * DM_ + wg);
        CPCOMMIT();
    }

    int p = 0;
    for (int c = 0; c < 16; c++) {
        CPWAIT0();
        __syncthreads();
        if (c < 15) {
            #pragma unroll
            for (int it = 0; it < 2; it++) {
                int r = sr + it*64;
                CPASYNC16(sb + (uint32_t)((((p^1)*5120) + r*XF + sc) * 4),
                          X + (size_t)(row0 + r) * DM_ + (c+1)*32 + sc);
            }
            CPASYNC16(sb + (uint32_t)((10240 + (p^1)*2560 + wr*WS) * 4 + wg*2),
                      Wh + (size_t)(col0 + wr) * DM_ + (c+1)*32 + wg);
            CPCOMMIT();
        }

        const float*    Xp = smf + p*5120;
        const uint32_t* Wp = smu + 10240 + p*2560;

        #pragma unroll
        for (int kk = 0; kk < 2; kk++) {
            uint32_t a[4];
            const float* xb = Xp + (m0 + lq)*XF + kk*16 + 2*lr;
            a[0] = ldsf2h(xb);
            a[1] = ldsf2h(xb + 8*XF);
            a[2] = ldsf2h(xb + 8);
            a[3] = ldsf2h(xb + 8*XF + 8);
            #pragma unroll
            for (int j = 0; j < 8; j++) {
                const uint32_t* wb = Wp + (n0 + j*8 + lq)*WS + kk*8 + lr;
                mma_f16(acc[j], a, wb[0], wb[4]);
            }
        }
        p ^= 1;
    }

    const int r0g = row0 + m0 + lq;
    const int r1g = r0g + 8;
    #pragma unroll
    for (int j = 0; j < 8; j++) {
        int jj = col0 + n0 + j*8 + 2*lr;
        float2 bs = *(const float2*)(bias + jj);
        bs.x *= bscl; bs.y *= bscl;
        int h = jj >> 6, d = jj & 63;
        {
            int b = r0g >> 11, n = r0g & 2047;
            uint32_t o = f2h2(acc[j][0] + bs.x, acc[j][1] + bs.y);
            *(uint32_t*)(outp + (((size_t)(b*H_ + h) * NQ_) + n) * HD_ + d) = o;
        }
        {
            int b = r1g >> 11, n = r1g & 2047;
            uint32_t o = f2h2(acc[j][2] + bs.x, acc[j][3] + bs.y);
            *(uint32_t*)(outp + (((size_t)(b*H_ + h) * NQ_) + n) * HD_ + d) = o;
        }
    }
}

// ---------------------------------------------------------------------------
// diag extraction
// ---------------------------------------------------------------------------
__global__ void diag_kernel(const float* __restrict__ pearson)
{
    int idx = blockIdx.x * 256 + threadIdx.x;
    if (idx < B_*H_*NK_) {
        int k  = idx & (NK_ - 1);
        int bh = idx >> 11;
        g_diag[idx] = pearson[((size_t)bh * NK_ + k) * NK_ + k];
    }
}

// ---------------------------------------------------------------------------
// Fused attention: fully cp.async-pipelined, P register-resident,
// QK B-frags via NON-TRANS ldmatrix.x4 (16 ldsm replace 64 LDS.32),
// scores arrive pre-scaled (EXP2C folded into Q projection).
// 256 threads (8 warps), 128 q-rows per CTA; 64-key tiles.
// smem words: KV[2]@0/4608, ds[2]@9216, mask[2]@9344/18048 -> 107008 B.
// grid (NQ/128, H, B)
// ---------------------------------------------------------------------------
#define KVS  4608
#define DS0  9216
#define MB0  9344
#define MB1  18048
#define ATTN_SMEM (26752 * 4)

__global__ __launch_bounds__(256) void attn_kernel(
    const float* __restrict__ mask, float* __restrict__ out)
{
    extern __shared__ uint32_t smu[];
    const uint32_t sb = smem_u32(smu);

    const int tid  = threadIdx.x;
    const int lane = tid & 31, warp = tid >> 5;
    const int lq = lane >> 2, lr = lane & 3;
    const int m0 = warp * 16;
    const int q0 = blockIdx.x * 128;
    const int h  = blockIdx.y;
    const int b  = blockIdx.z;
    const int bh = b * H_ + h;

    const __half* Qg = g_Q + (size_t)bh * NQ_ * HD_ + (size_t)q0 * HD_;
    const __half* Kg = g_K + (size_t)bh * NK_ * HD_;
    const __half* Vg = g_V + (size_t)bh * NK_ * HD_;
    const float*  dg = g_diag + (size_t)bh * NK_;
    const float*  mg = mask + ((size_t)bh * NQ_ + q0) * NK_;

    // staging coords
    const int sr  = tid >> 3;          // K/V rows 0..31, r = sr + it*32
    const int sc8 = (tid & 7) << 3;    // half col 0,8,..56
    const int msr = tid >> 4;          // mask rows 0..15, r = msr + it*16
    const int msc = (tid & 15) << 2;   // f32 col 0,4,..60

    // ---- stage Q into the MB0 area (scratch before mask uses it) ----
    #pragma unroll
    for (int it = 0; it < 4; it++) {
        int e = it*256 + tid;
        int r = e >> 3, c8 = (e & 7) << 3;
        *(uint4*)&smu[MB0 + r*SH2 + (c8 >> 1)] = *(const uint4*)(Qg + (size_t)r * HD_ + c8);
    }
    __syncthreads();

    uint32_t qf[4][4];
    #pragma unroll
    for (int kk = 0; kk < 4; kk++) {
        int ab = MB0 + (m0 + lq)*SH2 + kk*8 + lr;
        qf[kk][0] = smu[ab];
        qf[kk][1] = smu[ab + 8*SH2];
        qf[kk][2] = smu[ab + 4];
        qf[kk][3] = smu[ab + 8*SH2 + 4];
    }
    __syncthreads();   // everyone done reading MB0 before cp.async overwrites

    // shared ldmatrix lane offset (16 rows x 2 16B-chunks pattern)
    const uint32_t lm_lane = (uint32_t)(lane & 15) * (SH2*4)
                           + (uint32_t)(lane >> 4) * 16;

    float lsum0 = 0.f, lsum1 = 0.f;
    float oacc[8][4];
    #pragma unroll
    for (int j = 0; j < 8; j++)
        #pragma unroll
        for (int i = 0; i < 4; i++) oacc[j][i] = 0.f;

    // ---- prologue: group 0 = tile 0 (K/V/diag/mask) into parity 0 ----
    {
        #pragma unroll
        for (int it = 0; it < 2; it++) {
            int r = sr + it*32;
            CPASYNC16(sb + (uint32_t)((r*SH2 + (sc8>>1)) * 4),
                      Kg + (size_t)r * HD_ + sc8);
            CPASYNC16(sb + (uint32_t)((2304 + r*SH2 + (sc8>>1)) * 4),
                      Vg + (size_t)r * HD_ + sc8);
        }
        if (tid < 16)
            CPASYNC16(sb + (uint32_t)((DS0 + tid*4) * 4), dg + tid*4);
        #pragma unroll
        for (int it = 0; it < 8; it++) {
            int r = msr + it*16;
            CPASYNC16(sb + (uint32_t)((MB0 + r*MS + msc) * 4),
                      mg + (size_t)r * NK_ + msc);
        }
        CPCOMMIT();
    }

    for (int kt = 0; kt < NK_/64; kt++) {
        const int p = kt & 1;
        __syncthreads();   // all warps done reading parity p^1 buffers

        if (kt < NK_/64 - 1) {
            const int q2 = p ^ 1;
            const __half* Kt = Kg + (size_t)(kt+1) * 64 * HD_;
            const __half* Vt = Vg + (size_t)(kt+1) * 64 * HD_;
            const float*  mn = mg + (size_t)(kt+1) * 64;
            #pragma unroll
            for (int it = 0; it < 2; it++) {
                int r = sr + it*32;
                CPASYNC16(sb + (uint32_t)((q2*KVS + r*SH2 + (sc8>>1)) * 4),
                          Kt + (size_t)r * HD_ + sc8);
                CPASYNC16(sb + (uint32_t)((q2*KVS + 2304 + r*SH2 + (sc8>>1)) * 4),
                          Vt + (size_t)r * HD_ + sc8);
            }
            if (tid < 16)
                CPASYNC16(sb + (uint32_t)((DS0 + q2*64 + tid*4) * 4),
                          dg + (size_t)(kt+1)*64 + tid*4);
            #pragma unroll
            for (int it = 0; it < 8; it++) {
                int r = msr + it*16;
                CPASYNC16(sb + (uint32_t)(((q2 ? MB1 : MB0) + r*MS + msc) * 4),
                          mn + (size_t)r * NK_ + msc);
            }
            CPCOMMIT();
            CPWAIT1();      // current tile's group arrived; next stays in flight
        } else {
            CPWAIT0();
        }
        __syncthreads();

        const uint32_t  ksb = sb + (uint32_t)((p*KVS) * 4) + lm_lane;
        const uint32_t  vsb = sb + (uint32_t)((p*KVS + 2304) * 4) + lm_lane;
        const float*    dsp = (const float*)(smu + DS0 + p*64);
        const float*    msk = (const float*)(smu + (p ? MB1 : MB0));

        // ---- S = Q @ K^T  (B-frags via non-trans ldmatrix.x4) ----
        float sacc[8][4];
        #pragma unroll
        for (int j = 0; j < 8; j++)
            #pragma unroll
            for (int i = 0; i < 4; i++) sacc[j][i] = 0.f;

        #pragma unroll
        for (int kk = 0; kk < 4; kk++) {
            #pragma unroll
            for (int jj = 0; jj < 4; jj++) {
                uint32_t kb[4];
                ldsm_x4(kb, ksb + (uint32_t)jj*(16*SH2*4) + (uint32_t)kk*32);
                mma_f16(sacc[2*jj],     qf[kk], kb[0], kb[2]);
                mma_f16(sacc[2*jj + 1], qf[kk], kb[1], kb[3]);
            }
        }

        // ---- fixed-base softmax (pre-scaled) + mask*diag, P in registers ----
        const float* mp0 = msk + (m0 + lq)*MS + 2*lr;
        const float* mp1 = mp0 + 8*MS;
        #pragma unroll
        for (int j = 0; j < 8; j++) {
            float2 mk0 = *(const float2*)(mp0 + j*8);
            float2 mk1 = *(const float2*)(mp1 + j*8);
            float2 d2  = *(const float2*)(dsp + j*8 + 2*lr);
            float p0 = fast_ex2(sacc[j][0]);
            float p1 = fast_ex2(sacc[j][1]);
            float p2 = fast_ex2(sacc[j][2]);
            float p3 = fast_ex2(sacc[j][3]);
            lsum0 += p0 + p1;
            lsum1 += p2 + p3;
            sacc[j][0] = p0 * mk0.x * d2.x;
            sacc[j][1] = p1 * mk0.y * d2.y;
            sacc[j][2] = p2 * mk1.x * d2.x;
            sacc[j][3] = p3 * mk1.y * d2.y;
        }

        // ---- O += P @ V  (A-frags packed directly from C-frags of S) ----
        #pragma unroll
        for (int kk = 0; kk < 4; kk++) {
            uint32_t pa[4];
            pa[0] = f2h2(sacc[2*kk][0],   sacc[2*kk][1]);
            pa[1] = f2h2(sacc[2*kk][2],   sacc[2*kk][3]);
            pa[2] = f2h2(sacc[2*kk+1][0], sacc[2*kk+1][1]);
            pa[3] = f2h2(sacc[2*kk+1][2], sacc[2*kk+1][3]);
            #pragma unroll
            for (int jp = 0; jp < 4; jp++) {
                uint32_t vb[4];
                ldsm_x4_t(vb, vsb + (uint32_t)kk*(16*SH2*4) + (uint32_t)jp*32);
                mma_f16(oacc[2*jp],     pa, vb[0], vb[1]);
                mma_f16(oacc[2*jp + 1], pa, vb[2], vb[3]);
            }
        }
    }

    // ---- final l reduction over the quad and store ----
    lsum0 += __shfl_xor_sync(0xffffffffu, lsum0, 1);
    lsum0 += __shfl_xor_sync(0xffffffffu, lsum0, 2);
    lsum1 += __shfl_xor_sync(0xffffffffu, lsum1, 1);
    lsum1 += __shfl_xor_sync(0xffffffffu, lsum1, 2);
    float inv0 = 1.f / lsum0;
    float inv1 = 1.f / lsum1;

    const int r0 = q0 + m0 + lq;
    const int r1 = r0 + 8;
    #pragma unroll
    for (int j = 0; j < 8; j++) {
        int c = h*HD_ + j*8 + 2*lr;
        float2 o0; o0.x = oacc[j][0]*inv0; o0.y = oacc[j][1]*inv0;
        float2 o1; o1.x = oacc[j][2]*inv1; o1.y = oacc[j][3]*inv1;
        *(float2*)(out + ((size_t)b*NQ_ + r0)*DM_ + c) = o0;
        *(float2*)(out + ((size_t)b*NQ_ + r1)*DM_ + c) = o1;
    }
}

// ---------------------------------------------------------------------------
extern "C" void kernel_launch(void* const* d_in, const int* in_sizes, int n_in,
                              void* d_out, int out_size)
{
    const float* q       = (const float*)d_in[0];
    const float* k       = (const float*)d_in[1];
    const float* v       = (const float*)d_in[2];
    const float* mask    = (const float*)d_in[3];
    const float* pearson = (const float*)d_in[4];
    const float* Wq      = (const float*)d_in[5];
    const float* bq      = (const float*)d_in[6];
    const float* Wk      = (const float*)d_in[7];
    const float* bk      = (const float*)d_in[8];
    const float* Wv      = (const float*)d_in[9];
    const float* bv      = (const float*)d_in[10];
    float* out = (float*)d_out;

    cudaFuncSetAttribute(proj_kernel,
                         cudaFuncAttributeMaxDynamicSharedMemorySize, PROJ_SMEM);
    cudaFuncSetAttribute(attn_kernel,
                         cudaFuncAttributeMaxDynamicSharedMemorySize, ATTN_SMEM);

    wcvt_kernel<<<768, 256>>>(Wq, Wk, Wv);
    diag_kernel<<<(B_*H_*NK_ + 255)/256, 256>>>(pearson);

    dim3 pg(DM_/128, (B_*NQ_)/128, 3);
    proj_kernel<<<pg, 512, PROJ_SMEM>>>(q, k, v, bq, bk, bv);

    dim3 ag(NQ_/128, H_, B_);
    attn_kernel<<<ag, 256, ATTN_SMEM>>>(mask, out);
}

// round 16
// speedup vs baseline: 1.1072x; 1.1072x over previous
#include <cuda_runtime.h>
#include <cuda_fp16.h>
#include <math.h>
#include <stdint.h>

#define B_   2
#define H_   8
#define NQ_  2048
#define NK_  2048
#define DM_  512
#define HD_  64
#define EXP2C 0.18033688011112042f   /* 0.125 * log2(e) */

#define SH2 36   // half2 words per 64-half row; 36%32==4 -> conflict-free frags
#define XF  40   // f32 words per 32-f32 row; conflict-free float2 frags
#define WS  20   // uint32 words per 32-half W row
#define MS  68   // f32 words per 64-f32 mask row; 68%32==4 -> <=2-way on float2

// Scratch (allocation-free rule: __device__ globals)
__device__ __half g_Q[B_*H_*NQ_*HD_];
__device__ __half g_K[B_*H_*NK_*HD_];
__device__ __half g_V[B_*H_*NK_*HD_];
__device__ __half g_Wh[3*DM_*DM_];
__device__ float  g_diag[B_*H_*NK_];

// ---------------------------------------------------------------------------
// helpers
// ---------------------------------------------------------------------------
__device__ __forceinline__ float fast_ex2(float x) {
    float y;
    asm("ex2.approx.ftz.f32 %0, %1;" : "=f"(y) : "f"(x));
    return y;
}
__device__ __forceinline__ uint32_t f2h2(float lo, float hi) {
    __half2 h = __floats2half2_rn(lo, hi);
    return *reinterpret_cast<uint32_t*>(&h);
}
__device__ __forceinline__ uint32_t ldsf2h(const float* p) {
    float2 v = *(const float2*)p;
    return f2h2(v.x, v.y);
}
__device__ __forceinline__ void mma_f16(float c[4], const uint32_t a[4],
                                        uint32_t b0, uint32_t b1) {
    asm volatile(
        "mma.sync.aligned.m16n8k16.row.col.f32.f16.f16.f32 "
        "{%0,%1,%2,%3}, {%4,%5,%6,%7}, {%8,%9}, {%0,%1,%2,%3};\n"
        : "+f"(c[0]), "+f"(c[1]), "+f"(c[2]), "+f"(c[3])
        : "r"(a[0]), "r"(a[1]), "r"(a[2]), "r"(a[3]), "r"(b0), "r"(b1));
}
__device__ __forceinline__ void ldsm_x4_t(uint32_t r[4], uint32_t addr) {
    asm volatile(
        "ldmatrix.sync.aligned.m8n8.x4.trans.shared.b16 {%0,%1,%2,%3}, [%4];"
        : "=r"(r[0]), "=r"(r[1]), "=r"(r[2]), "=r"(r[3]) : "r"(addr));
}
__device__ __forceinline__ uint32_t smem_u32(const void* p) {
    uint32_t a;
    asm("{ .reg .u64 t; cvta.to.shared.u64 t, %1; cvt.u32.u64 %0, t; }"
        : "=r"(a) : "l"(p));
    return a;
}
#define CPASYNC16(dst, src) \
    asm volatile("cp.async.cg.shared.global [%0], [%1], 16;" :: "r"(dst), "l"(src))
#define CPCOMMIT()  asm volatile("cp.async.commit_group;" ::: "memory")
#define CPWAIT0()   asm volatile("cp.async.wait_group 0;"  ::: "memory")
#define CPWAIT1()   asm volatile("cp.async.wait_group 1;"  ::: "memory")

// ---------------------------------------------------------------------------
// W fp32 -> fp16 pre-convert. Wq additionally scaled by EXP2C so attention
// scores come out pre-scaled in log2 domain.
// ---------------------------------------------------------------------------
__global__ void wcvt_kernel(const float* __restrict__ Wq,
                            const float* __restrict__ Wk,
                            const float* __restrict__ Wv)
{
    int idx = blockIdx.x * 256 + threadIdx.x;        // 0 .. 196607 (float4)
    const float* src = (idx < 65536) ? Wq : (idx < 131072 ? Wk : Wv);
    float s = (idx < 65536) ? EXP2C : 1.0f;
    float4 w = *(const float4*)(src + (size_t)(idx & 65535) * 4);
    uint2 o;
    o.x = f2h2(w.x * s, w.y * s);
    o.y = f2h2(w.z * s, w.w * s);
    *(uint2*)(g_Wh + (size_t)idx * 4) = o;
}

// ---------------------------------------------------------------------------
// Projection: fp16 m16n8k16, cp.async double-buffered, 512 threads.
// Bias for the Q projection scaled by EXP2C to match scaled Wq.
// ---------------------------------------------------------------------------
#define PROJ_SMEM (15360 * 4)

__global__ __launch_bounds__(512) void proj_kernel(
    const float* __restrict__ q, const float* __restrict__ k,
    const float* __restrict__ v,
    const float* __restrict__ bq, const float* __restrict__ bk,
    const float* __restrict__ bv)
{
    extern __shared__ float smf[];
    uint32_t* smu = (uint32_t*)smf;
    const uint32_t sb = smem_u32(smf);

    const float *X, *bias;
    const __half* Wh;
    __half* outp;
    float bscl = 1.0f;
    if (blockIdx.z == 0)      { X = q; bias = bq; Wh = g_Wh;              outp = g_Q; bscl = EXP2C; }
    else if (blockIdx.z == 1) { X = k; bias = bk; Wh = g_Wh + DM_*DM_;    outp = g_K; }
    else                      { X = v; bias = bv; Wh = g_Wh + 2*DM_*DM_;  outp = g_V; }

    const int tid  = threadIdx.x;
    const int lane = tid & 31, warp = tid >> 5;
    const int lq = lane >> 2, lr = lane & 3;
    const int m0 = (warp & 7) * 16;
    const int n0 = (warp >> 3) * 64;
    const int row0 = blockIdx.y * 128;
    const int col0 = blockIdx.x * 128;

    const int sr = tid >> 3;
    const int sc = (tid & 7) << 2;
    const int wr = tid >> 2;
    const int wg = (tid & 3) << 3;

    float acc[8][4];
    #pragma unroll
    for (int j = 0; j < 8; j++)
        #pragma unroll
        for (int i = 0; i < 4; i++) acc[j][i] = 0.f;

    {
        #pragma unroll
        for (int it = 0; it < 2; it++) {
            int r = sr + it*64;
            CPASYNC16(sb + (uint32_t)((r*XF + sc) * 4),
                      X + (size_t)(row0 + r) * DM_ + sc);
        }
        CPASYNC16(sb + (uint32_t)((10240 + wr*WS) * 4 + wg*2),
                  Wh + (size_t)(col0 + wr) * DM_ + wg);
        CPCOMMIT();
    }

    int p = 0;
    for (int c = 0; c < 16; c++) {
        CPWAIT0();
        __syncthreads();
        if (c < 15) {
            #pragma unroll
            for (int it = 0; it < 2; it++) {
                int r = sr + it*64;
                CPASYNC16(sb + (uint32_t)((((p^1)*5120) + r*XF + sc) * 4),
                          X + (size_t)(row0 + r) * DM_ + (c+1)*32 + sc);
            }
            CPASYNC16(sb + (uint32_t)((10240 + (p^1)*2560 + wr*WS) * 4 + wg*2),
                      Wh + (size_t)(col0 + wr) * DM_ + (c+1)*32 + wg);
            CPCOMMIT();
        }

        const float*    Xp = smf + p*5120;
        const uint32_t* Wp = smu + 10240 + p*2560;

        #pragma unroll
        for (int kk = 0; kk < 2; kk++) {
            uint32_t a[4];
            const float* xb = Xp + (m0 + lq)*XF + kk*16 + 2*lr;
            a[0] = ldsf2h(xb);
            a[1] = ldsf2h(xb + 8*XF);
            a[2] = ldsf2h(xb + 8);
            a[3] = ldsf2h(xb + 8*XF + 8);
            #pragma unroll
            for (int j = 0; j < 8; j++) {
                const uint32_t* wb = Wp + (n0 + j*8 + lq)*WS + kk*8 + lr;
                mma_f16(acc[j], a, wb[0], wb[4]);
            }
        }
        p ^= 1;
    }

    const int r0g = row0 + m0 + lq;
    const int r1g = r0g + 8;
    #pragma unroll
    for (int j = 0; j < 8; j++) {
        int jj = col0 + n0 + j*8 + 2*lr;
        float2 bs = *(const float2*)(bias + jj);
        bs.x *= bscl; bs.y *= bscl;
        int h = jj >> 6, d = jj & 63;
        {
            int b = r0g >> 11, n = r0g & 2047;
            uint32_t o = f2h2(acc[j][0] + bs.x, acc[j][1] + bs.y);
            *(uint32_t*)(outp + (((size_t)(b*H_ + h) * NQ_) + n) * HD_ + d) = o;
        }
        {
            int b = r1g >> 11, n = r1g & 2047;
            uint32_t o = f2h2(acc[j][2] + bs.x, acc[j][3] + bs.y);
            *(uint32_t*)(outp + (((size_t)(b*H_ + h) * NQ_) + n) * HD_ + d) = o;
        }
    }
}

// ---------------------------------------------------------------------------
// diag extraction
// ---------------------------------------------------------------------------
__global__ void diag_kernel(const float* __restrict__ pearson)
{
    int idx = blockIdx.x * 256 + threadIdx.x;
    if (idx < B_*H_*NK_) {
        int k  = idx & (NK_ - 1);
        int bh = idx >> 11;
        g_diag[idx] = pearson[((size_t)bh * NK_ + k) * NK_ + k];
    }
}

// ---------------------------------------------------------------------------
// Fused attention (R14 structure, the 86-reg / 95.4us configuration):
// fully cp.async-pipelined, P register-resident, scalar-LDS QK B-frags,
// scores pre-scaled via folded EXP2C.  __launch_bounds__(256,2) pins
// residency at 2 CTAs/SM (regs <= 128) — the R15 ldsm variant silently
// blew to 130 regs / 1 CTA and regressed.
// smem words: KV[2]@0/4608, ds[2]@9216, mask[2]@9344/18048 -> 107008 B.
// grid (NQ/128, H, B)
// ---------------------------------------------------------------------------
#define KVS  4608
#define DS0  9216
#define MB0  9344
#define MB1  18048
#define ATTN_SMEM (26752 * 4)

__global__ __launch_bounds__(256, 2) void attn_kernel(
    const float* __restrict__ mask, float* __restrict__ out)
{
    extern __shared__ uint32_t smu[];
    const uint32_t sb = smem_u32(smu);

    const int tid  = threadIdx.x;
    const int lane = tid & 31, warp = tid >> 5;
    const int lq = lane >> 2, lr = lane & 3;
    const int m0 = warp * 16;
    const int q0 = blockIdx.x * 128;
    const int h  = blockIdx.y;
    const int b  = blockIdx.z;
    const int bh = b * H_ + h;

    const __half* Qg = g_Q + (size_t)bh * NQ_ * HD_ + (size_t)q0 * HD_;
    const __half* Kg = g_K + (size_t)bh * NK_ * HD_;
    const __half* Vg = g_V + (size_t)bh * NK_ * HD_;
    const float*  dg = g_diag + (size_t)bh * NK_;
    const float*  mg = mask + ((size_t)bh * NQ_ + q0) * NK_;

    // staging coords
    const int sr  = tid >> 3;          // K/V rows 0..31, r = sr + it*32
    const int sc8 = (tid & 7) << 3;    // half col 0,8,..56
    const int msr = tid >> 4;          // mask rows 0..15, r = msr + it*16
    const int msc = (tid & 15) << 2;   // f32 col 0,4,..60

    // ---- stage Q into the MB0 area (scratch before mask uses it) ----
    #pragma unroll
    for (int it = 0; it < 4; it++) {
        int e = it*256 + tid;
        int r = e >> 3, c8 = (e & 7) << 3;
        *(uint4*)&smu[MB0 + r*SH2 + (c8 >> 1)] = *(const uint4*)(Qg + (size_t)r * HD_ + c8);
    }
    __syncthreads();

    uint32_t qf[4][4];
    #pragma unroll
    for (int kk = 0; kk < 4; kk++) {
        int ab = MB0 + (m0 + lq)*SH2 + kk*8 + lr;
        qf[kk][0] = smu[ab];
        qf[kk][1] = smu[ab + 8*SH2];
        qf[kk][2] = smu[ab + 4];
        qf[kk][3] = smu[ab + 8*SH2 + 4];
    }
    __syncthreads();   // everyone done reading MB0 before cp.async overwrites

    const uint32_t vs_lane = (uint32_t)(lane & 15) * (SH2*4)
                           + (uint32_t)(lane >> 4) * 16;

    float lsum0 = 0.f, lsum1 = 0.f;
    float oacc[8][4];
    #pragma unroll
    for (int j = 0; j < 8; j++)
        #pragma unroll
        for (int i = 0; i < 4; i++) oacc[j][i] = 0.f;

    // ---- prologue: group 0 = tile 0 (K/V/diag/mask) into parity 0 ----
    {
        #pragma unroll
        for (int it = 0; it < 2; it++) {
            int r = sr + it*32;
            CPASYNC16(sb + (uint32_t)((r*SH2 + (sc8>>1)) * 4),
                      Kg + (size_t)r * HD_ + sc8);
            CPASYNC16(sb + (uint32_t)((2304 + r*SH2 + (sc8>>1)) * 4),
                      Vg + (size_t)r * HD_ + sc8);
        }
        if (tid < 16)
            CPASYNC16(sb + (uint32_t)((DS0 + tid*4) * 4), dg + tid*4);
        #pragma unroll
        for (int it = 0; it < 8; it++) {
            int r = msr + it*16;
            CPASYNC16(sb + (uint32_t)((MB0 + r*MS + msc) * 4),
                      mg + (size_t)r * NK_ + msc);
        }
        CPCOMMIT();
    }

    for (int kt = 0; kt < NK_/64; kt++) {
        const int p = kt & 1;
        __syncthreads();   // all warps done reading parity p^1 buffers

        if (kt < NK_/64 - 1) {
            const int q2 = p ^ 1;
            const __half* Kt = Kg + (size_t)(kt+1) * 64 * HD_;
            const __half* Vt = Vg + (size_t)(kt+1) * 64 * HD_;
            const float*  mn = mg + (size_t)(kt+1) * 64;
            #pragma unroll
            for (int it = 0; it < 2; it++) {
                int r = sr + it*32;
                CPASYNC16(sb + (uint32_t)((q2*KVS + r*SH2 + (sc8>>1)) * 4),
                          Kt + (size_t)r * HD_ + sc8);
                CPASYNC16(sb + (uint32_t)((q2*KVS + 2304 + r*SH2 + (sc8>>1)) * 4),
                          Vt + (size_t)r * HD_ + sc8);
            }
            if (tid < 16)
                CPASYNC16(sb + (uint32_t)((DS0 + q2*64 + tid*4) * 4),
                          dg + (size_t)(kt+1)*64 + tid*4);
            #pragma unroll
            for (int it = 0; it < 8; it++) {
                int r = msr + it*16;
                CPASYNC16(sb + (uint32_t)(((q2 ? MB1 : MB0) + r*MS + msc) * 4),
                          mn + (size_t)r * NK_ + msc);
            }
            CPCOMMIT();
            CPWAIT1();      // current tile's group arrived; next stays in flight
        } else {
            CPWAIT0();
        }
        __syncthreads();

        const uint32_t* Ksp = smu + p*KVS;
        const uint32_t  vsb = sb + (uint32_t)((p*KVS + 2304) * 4) + vs_lane;
        const float*    dsp = (const float*)(smu + DS0 + p*64);
        const float*    msk = (const float*)(smu + (p ? MB1 : MB0));

        // ---- S = Q @ K^T (scalar-LDS B-frags; proven 86-reg path) ----
        float sacc[8][4];
        #pragma unroll
        for (int j = 0; j < 8; j++)
            #pragma unroll
            for (int i = 0; i < 4; i++) sacc[j][i] = 0.f;

        #pragma unroll
        for (int kk = 0; kk < 4; kk++) {
            #pragma unroll
            for (int j = 0; j < 8; j++) {
                int bb = (j*8 + lq)*SH2 + kk*8 + lr;
                mma_f16(sacc[j], qf[kk], Ksp[bb], Ksp[bb + 4]);
            }
        }

        // ---- fixed-base softmax (pre-scaled) + mask*diag, P in registers ----
        const float* mp0 = msk + (m0 + lq)*MS + 2*lr;
        const float* mp1 = mp0 + 8*MS;
        #pragma unroll
        for (int j = 0; j < 8; j++) {
            float2 mk0 = *(const float2*)(mp0 + j*8);
            float2 mk1 = *(const float2*)(mp1 + j*8);
            float2 d2  = *(const float2*)(dsp + j*8 + 2*lr);
            float p0 = fast_ex2(sacc[j][0]);
            float p1 = fast_ex2(sacc[j][1]);
            float p2 = fast_ex2(sacc[j][2]);
            float p3 = fast_ex2(sacc[j][3]);
            lsum0 += p0 + p1;
            lsum1 += p2 + p3;
            sacc[j][0] = p0 * mk0.x * d2.x;
            sacc[j][1] = p1 * mk0.y * d2.y;
            sacc[j][2] = p2 * mk1.x * d2.x;
            sacc[j][3] = p3 * mk1.y * d2.y;
        }

        // ---- O += P @ V  (A-frags packed directly from C-frags of S) ----
        #pragma unroll
        for (int kk = 0; kk < 4; kk++) {
            uint32_t pa[4];
            pa[0] = f2h2(sacc[2*kk][0],   sacc[2*kk][1]);
            pa[1] = f2h2(sacc[2*kk][2],   sacc[2*kk][3]);
            pa[2] = f2h2(sacc[2*kk+1][0], sacc[2*kk+1][1]);
            pa[3] = f2h2(sacc[2*kk+1][2], sacc[2*kk+1][3]);
            #pragma unroll
            for (int jp = 0; jp < 4; jp++) {
                uint32_t vb[4];
                ldsm_x4_t(vb, vsb + (uint32_t)kk*(16*SH2*4) + (uint32_t)jp*32);
                mma_f16(oacc[2*jp],     pa, vb[0], vb[1]);
                mma_f16(oacc[2*jp + 1], pa, vb[2], vb[3]);
            }
        }
    }

    // ---- final l reduction over the quad and store ----
    lsum0 += __shfl_xor_sync(0xffffffffu, lsum0, 1);
    lsum0 += __shfl_xor_sync(0xffffffffu, lsum0, 2);
    lsum1 += __shfl_xor_sync(0xffffffffu, lsum1, 1);
    lsum1 += __shfl_xor_sync(0xffffffffu, lsum1, 2);
    float inv0 = 1.f / lsum0;
    float inv1 = 1.f / lsum1;

    const int r0 = q0 + m0 + lq;
    const int r1 = r0 + 8;
    #pragma unroll
    for (int j = 0; j < 8; j++) {
        int c = h*HD_ + j*8 + 2*lr;
        float2 o0; o0.x = oacc[j][0]*inv0; o0.y = oacc[j][1]*inv0;
        float2 o1; o1.x = oacc[j][2]*inv1; o1.y = oacc[j][3]*inv1;
        *(float2*)(out + ((size_t)b*NQ_ + r0)*DM_ + c) = o0;
        *(float2*)(out + ((size_t)b*NQ_ + r1)*DM_ + c) = o1;
    }
}

// ---------------------------------------------------------------------------
extern "C" void kernel_launch(void* const* d_in, const int* in_sizes, int n_in,
                              void* d_out, int out_size)
{
    const float* q       = (const float*)d_in[0];
    const float* k       = (const float*)d_in[1];
    const float* v       = (const float*)d_in[2];
    const float* mask    = (const float*)d_in[3];
    const float* pearson = (const float*)d_in[4];
    const float* Wq      = (const float*)d_in[5];
    const float* bq      = (const float*)d_in[6];
    const float* Wk      = (const float*)d_in[7];
    const float* bk      = (const float*)d_in[8];
    const float* Wv      = (const float*)d_in[9];
    const float* bv      = (const float*)d_in[10];
    float* out = (float*)d_out;

    cudaFuncSetAttribute(proj_kernel,
                         cudaFuncAttributeMaxDynamicSharedMemorySize, PROJ_SMEM);
    cudaFuncSetAttribute(attn_kernel,
                         cudaFuncAttributeMaxDynamicSharedMemorySize, ATTN_SMEM);

    wcvt_kernel<<<768, 256>>>(Wq, Wk, Wv);
    diag_kernel<<<(B_*H_*NK_ + 255)/256, 256>>>(pearson);

    dim3 pg(DM_/128, (B_*NQ_)/128, 3);
    proj_kernel<<<pg, 512, PROJ_SMEM>>>(q, k, v, bq, bk, bv);

    dim3 ag(NQ_/128, H_, B_);
    attn_kernel<<<ag, 256, ATTN_SMEM>>>(mask, out);
}

// round 17
// speedup vs baseline: 1.1121x; 1.0044x over previous
#include <cuda_runtime.h>
#include <cuda_fp16.h>
#include <math.h>
#include <stdint.h>

#define B_   2
#define H_   8
#define NQ_  2048
#define NK_  2048
#define DM_  512
#define HD_  64
#define EXP2C 0.18033688011112042f   /* 0.125 * log2(e) */

#define SH2 36   // half2 words per 64-half row; 36%32==4 -> conflict-free frags
#define XF  40   // f32 words per 32-f32 row; conflict-free float2 frags
#define WS  20   // uint32 words per 32-half W row
#define MS  68   // f32 words per 64-f32 mask row; 68%32==4 -> <=2-way on float2

// Scratch (allocation-free rule: __device__ globals)
__device__ __half g_Q[B_*H_*NQ_*HD_];
__device__ __half g_K[B_*H_*NK_*HD_];
__device__ __half g_V[B_*H_*NK_*HD_];
__device__ __half g_Wh[3*DM_*DM_];
__device__ float  g_diag[B_*H_*NK_];

// ---------------------------------------------------------------------------
// helpers
// ---------------------------------------------------------------------------
__device__ __forceinline__ float fast_ex2(float x) {
    float y;
    asm("ex2.approx.ftz.f32 %0, %1;" : "=f"(y) : "f"(x));
    return y;
}
__device__ __forceinline__ uint32_t f2h2(float lo, float hi) {
    __half2 h = __floats2half2_rn(lo, hi);
    return *reinterpret_cast<uint32_t*>(&h);
}
__device__ __forceinline__ uint32_t ldsf2h(const float* p) {
    float2 v = *(const float2*)p;
    return f2h2(v.x, v.y);
}
__device__ __forceinline__ void mma_f16(float c[4], const uint32_t a[4],
                                        uint32_t b0, uint32_t b1) {
    asm volatile(
        "mma.sync.aligned.m16n8k16.row.col.f32.f16.f16.f32 "
        "{%0,%1,%2,%3}, {%4,%5,%6,%7}, {%8,%9}, {%0,%1,%2,%3};\n"
        : "+f"(c[0]), "+f"(c[1]), "+f"(c[2]), "+f"(c[3])
        : "r"(a[0]), "r"(a[1]), "r"(a[2]), "r"(a[3]), "r"(b0), "r"(b1));
}
__device__ __forceinline__ void ldsm_x4_t(uint32_t r[4], uint32_t addr) {
    asm volatile(
        "ldmatrix.sync.aligned.m8n8.x4.trans.shared.b16 {%0,%1,%2,%3}, [%4];"
        : "=r"(r[0]), "=r"(r[1]), "=r"(r[2]), "=r"(r[3]) : "r"(addr));
}
__device__ __forceinline__ void ldsm_x2(uint32_t r[2], uint32_t addr) {
    asm volatile(
        "ldmatrix.sync.aligned.m8n8.x2.shared.b16 {%0,%1}, [%2];"
        : "=r"(r[0]), "=r"(r[1]) : "r"(addr));
}
__device__ __forceinline__ uint32_t smem_u32(const void* p) {
    uint32_t a;
    asm("{ .reg .u64 t; cvta.to.shared.u64 t, %1; cvt.u32.u64 %0, t; }"
        : "=r"(a) : "l"(p));
    return a;
}
#define CPASYNC16(dst, src) \
    asm volatile("cp.async.cg.shared.global [%0], [%1], 16;" :: "r"(dst), "l"(src))
#define CPCOMMIT()  asm volatile("cp.async.commit_group;" ::: "memory")
#define CPWAIT0()   asm volatile("cp.async.wait_group 0;"  ::: "memory")
#define CPWAIT1()   asm volatile("cp.async.wait_group 1;"  ::: "memory")

// ---------------------------------------------------------------------------
// Fused prep: W fp32->fp16 (Wq scaled by EXP2C) + pearson diag extraction.
// blocks 0..767: W convert (float4 each thread); blocks 768..895: diag.
// ---------------------------------------------------------------------------
__global__ void prep_kernel(const float* __restrict__ Wq,
                            const float* __restrict__ Wk,
                            const float* __restrict__ Wv,
                            const float* __restrict__ pearson)
{
    if (blockIdx.x < 768) {
        int idx = blockIdx.x * 256 + threadIdx.x;        // 0 .. 196607 (float4)
        const float* src = (idx < 65536) ? Wq : (idx < 131072 ? Wk : Wv);
        float s = (idx < 65536) ? EXP2C : 1.0f;
        float4 w = *(const float4*)(src + (size_t)(idx & 65535) * 4);
        uint2 o;
        o.x = f2h2(w.x * s, w.y * s);
        o.y = f2h2(w.z * s, w.w * s);
        *(uint2*)(g_Wh + (size_t)idx * 4) = o;
    } else {
        int idx = (blockIdx.x - 768) * 256 + threadIdx.x;
        if (idx < B_*H_*NK_) {
            int k  = idx & (NK_ - 1);
            int bh = idx >> 11;
            g_diag[idx] = pearson[((size_t)bh * NK_ + k) * NK_ + k];
        }
    }
}

// ---------------------------------------------------------------------------
// Projection: fp16 m16n8k16, cp.async double-buffered, 512 threads.
// Bias for the Q projection scaled by EXP2C to match scaled Wq.
// ---------------------------------------------------------------------------
#define PROJ_SMEM (15360 * 4)

__global__ __launch_bounds__(512) void proj_kernel(
    const float* __restrict__ q, const float* __restrict__ k,
    const float* __restrict__ v,
    const float* __restrict__ bq, const float* __restrict__ bk,
    const float* __restrict__ bv)
{
    extern __shared__ float smf[];
    uint32_t* smu = (uint32_t*)smf;
    const uint32_t sb = smem_u32(smf);

    const float *X, *bias;
    const __half* Wh;
    __half* outp;
    float bscl = 1.0f;
    if (blockIdx.z == 0)      { X = q; bias = bq; Wh = g_Wh;              outp = g_Q; bscl = EXP2C; }
    else if (blockIdx.z == 1) { X = k; bias = bk; Wh = g_Wh + DM_*DM_;    outp = g_K; }
    else                      { X = v; bias = bv; Wh = g_Wh + 2*DM_*DM_;  outp = g_V; }

    const int tid  = threadIdx.x;
    const int lane = tid & 31, warp = tid >> 5;
    const int lq = lane >> 2, lr = lane & 3;
    const int m0 = (warp & 7) * 16;
    const int n0 = (warp >> 3) * 64;
    const int row0 = blockIdx.y * 128;
    const int col0 = blockIdx.x * 128;

    const int sr = tid >> 3;
    const int sc = (tid & 7) << 2;
    const int wr = tid >> 2;
    const int wg = (tid & 3) << 3;

    float acc[8][4];
    #pragma unroll
    for (int j = 0; j < 8; j++)
        #pragma unroll
        for (int i = 0; i < 4; i++) acc[j][i] = 0.f;

    {
        #pragma unroll
        for (int it = 0; it < 2; it++) {
            int r = sr + it*64;
            CPASYNC16(sb + (uint32_t)((r*XF + sc) * 4),
                      X + (size_t)(row0 + r) * DM_ + sc);
        }
        CPASYNC16(sb + (uint32_t)((10240 + wr*WS) * 4 + wg*2),
                  Wh + (size_t)(col0 + wr) * DM_ + wg);
        CPCOMMIT();
    }

    int p = 0;
    for (int c = 0; c < 16; c++) {
        CPWAIT0();
        __syncthreads();
        if (c < 15) {
            #pragma unroll
            for (int it = 0; it < 2; it++) {
                int r = sr + it*64;
                CPASYNC16(sb + (uint32_t)((((p^1)*5120) + r*XF + sc) * 4),
                          X + (size_t)(row0 + r) * DM_ + (c+1)*32 + sc);
            }
            CPASYNC16(sb + (uint32_t)((10240 + (p^1)*2560 + wr*WS) * 4 + wg*2),
                      Wh + (size_t)(col0 + wr) * DM_ + (c+1)*32 + wg);
            CPCOMMIT();
        }

        const float*    Xp = smf + p*5120;
        const uint32_t* Wp = smu + 10240 + p*2560;

        #pragma unroll
        for (int kk = 0; kk < 2; kk++) {
            uint32_t a[4];
            const float* xb = Xp + (m0 + lq)*XF + kk*16 + 2*lr;
            a[0] = ldsf2h(xb);
            a[1] = ldsf2h(xb + 8*XF);
            a[2] = ldsf2h(xb + 8);
            a[3] = ldsf2h(xb + 8*XF + 8);
            #pragma unroll
            for (int j = 0; j < 8; j++) {
                const uint32_t* wb = Wp + (n0 + j*8 + lq)*WS + kk*8 + lr;
                mma_f16(acc[j], a, wb[0], wb[4]);
            }
        }
        p ^= 1;
    }

    const int r0g = row0 + m0 + lq;
    const int r1g = r0g + 8;
    #pragma unroll
    for (int j = 0; j < 8; j++) {
        int jj = col0 + n0 + j*8 + 2*lr;
        float2 bs = *(const float2*)(bias + jj);
        bs.x *= bscl; bs.y *= bscl;
        int h = jj >> 6, d = jj & 63;
        {
            int b = r0g >> 11, n = r0g & 2047;
            uint32_t o = f2h2(acc[j][0] + bs.x, acc[j][1] + bs.y);
            *(uint32_t*)(outp + (((size_t)(b*H_ + h) * NQ_) + n) * HD_ + d) = o;
        }
        {
            int b = r1g >> 11, n = r1g & 2047;
            uint32_t o = f2h2(acc[j][2] + bs.x, acc[j][3] + bs.y);
            *(uint32_t*)(outp + (((size_t)(b*H_ + h) * NQ_) + n) * HD_ + d) = o;
        }
    }
}

// ---------------------------------------------------------------------------
// Fused attention: fully cp.async-pipelined, P register-resident, scores
// pre-scaled (EXP2C folded into Q projection).
// QK B-frags via ldmatrix.x2 NON-TRANS in the SAME loop nest as the proven
// scalar path (2 temps -> no register blowup; R15's x4 restructure hit 130
// regs and halved residency).  __launch_bounds__(256,2) pins regs <= 128.
// smem words: KV[2]@0/4608, ds[2]@9216, mask[2]@9344/18048 -> 107008 B.
// grid (NQ/128, H, B)
// ---------------------------------------------------------------------------
#define KVS  4608
#define DS0  9216
#define MB0  9344
#define MB1  18048
#define ATTN_SMEM (26752 * 4)

__global__ __launch_bounds__(256, 2) void attn_kernel(
    const float* __restrict__ mask, float* __restrict__ out)
{
    extern __shared__ uint32_t smu[];
    const uint32_t sb = smem_u32(smu);

    const int tid  = threadIdx.x;
    const int lane = tid & 31, warp = tid >> 5;
    const int lq = lane >> 2, lr = lane & 3;
    const int m0 = warp * 16;
    const int q0 = blockIdx.x * 128;
    const int h  = blockIdx.y;
    const int b  = blockIdx.z;
    const int bh = b * H_ + h;

    const __half* Qg = g_Q + (size_t)bh * NQ_ * HD_ + (size_t)q0 * HD_;
    const __half* Kg = g_K + (size_t)bh * NK_ * HD_;
    const __half* Vg = g_V + (size_t)bh * NK_ * HD_;
    const float*  dg = g_diag + (size_t)bh * NK_;
    const float*  mg = mask + ((size_t)bh * NQ_ + q0) * NK_;

    // staging coords
    const int sr  = tid >> 3;          // K/V rows 0..31, r = sr + it*32
    const int sc8 = (tid & 7) << 3;    // half col 0,8,..56
    const int msr = tid >> 4;          // mask rows 0..15, r = msr + it*16
    const int msc = (tid & 15) << 2;   // f32 col 0,4,..60

    // ---- stage Q into the MB0 area (scratch before mask uses it) ----
    #pragma unroll
    for (int it = 0; it < 4; it++) {
        int e = it*256 + tid;
        int r = e >> 3, c8 = (e & 7) << 3;
        *(uint4*)&smu[MB0 + r*SH2 + (c8 >> 1)] = *(const uint4*)(Qg + (size_t)r * HD_ + c8);
    }
    __syncthreads();

    uint32_t qf[4][4];
    #pragma unroll
    for (int kk = 0; kk < 4; kk++) {
        int ab = MB0 + (m0 + lq)*SH2 + kk*8 + lr;
        qf[kk][0] = smu[ab];
        qf[kk][1] = smu[ab + 8*SH2];
        qf[kk][2] = smu[ab + 4];
        qf[kk][3] = smu[ab + 8*SH2 + 4];
    }
    __syncthreads();   // everyone done reading MB0 before cp.async overwrites

    // ldmatrix lane offsets
    const uint32_t vs_lane  = (uint32_t)(lane & 15) * (SH2*4)
                            + (uint32_t)(lane >> 4) * 16;          // x4 trans (V)
    const uint32_t km_lane  = (uint32_t)(lane & 7) * (SH2*4)
                            + (uint32_t)((lane >> 3) & 1) * 16;    // x2 non-trans (K)

    float lsum0 = 0.f, lsum1 = 0.f;
    float oacc[8][4];
    #pragma unroll
    for (int j = 0; j < 8; j++)
        #pragma unroll
        for (int i = 0; i < 4; i++) oacc[j][i] = 0.f;

    // ---- prologue: group 0 = tile 0 (K/V/diag/mask) into parity 0 ----
    {
        #pragma unroll
        for (int it = 0; it < 2; it++) {
            int r = sr + it*32;
            CPASYNC16(sb + (uint32_t)((r*SH2 + (sc8>>1)) * 4),
                      Kg + (size_t)r * HD_ + sc8);
            CPASYNC16(sb + (uint32_t)((2304 + r*SH2 + (sc8>>1)) * 4),
                      Vg + (size_t)r * HD_ + sc8);
        }
        if (tid < 16)
            CPASYNC16(sb + (uint32_t)((DS0 + tid*4) * 4), dg + tid*4);
        #pragma unroll
        for (int it = 0; it < 8; it++) {
            int r = msr + it*16;
            CPASYNC16(sb + (uint32_t)((MB0 + r*MS + msc) * 4),
                      mg + (size_t)r * NK_ + msc);
        }
        CPCOMMIT();
    }

    for (int kt = 0; kt < NK_/64; kt++) {
        const int p = kt & 1;
        __syncthreads();   // all warps done reading parity p^1 buffers

        if (kt < NK_/64 - 1) {
            const int q2 = p ^ 1;
            const __half* Kt = Kg + (size_t)(kt+1) * 64 * HD_;
            const __half* Vt = Vg + (size_t)(kt+1) * 64 * HD_;
            const float*  mn = mg + (size_t)(kt+1) * 64;
            #pragma unroll
            for (int it = 0; it < 2; it++) {
                int r = sr + it*32;
                CPASYNC16(sb + (uint32_t)((q2*KVS + r*SH2 + (sc8>>1)) * 4),
                          Kt + (size_t)r * HD_ + sc8);
                CPASYNC16(sb + (uint32_t)((q2*KVS + 2304 + r*SH2 + (sc8>>1)) * 4),
                          Vt + (size_t)r * HD_ + sc8);
            }
            if (tid < 16)
                CPASYNC16(sb + (uint32_t)((DS0 + q2*64 + tid*4) * 4),
                          dg + (size_t)(kt+1)*64 + tid*4);
            #pragma unroll
            for (int it = 0; it < 8; it++) {
                int r = msr + it*16;
                CPASYNC16(sb + (uint32_t)(((q2 ? MB1 : MB0) + r*MS + msc) * 4),
                          mn + (size_t)r * NK_ + msc);
            }
            CPCOMMIT();
            CPWAIT1();      // current tile's group arrived; next stays in flight
        } else {
            CPWAIT0();
        }
        __syncthreads();

        const uint32_t  ksb = sb + (uint32_t)((p*KVS) * 4) + km_lane;
        const uint32_t  vsb = sb + (uint32_t)((p*KVS + 2304) * 4) + vs_lane;
        const float*    dsp = (const float*)(smu + DS0 + p*64);
        const float*    msk = (const float*)(smu + (p ? MB1 : MB0));

        // ---- S = Q @ K^T  (B-frags via ldmatrix.x2 non-trans) ----
        float sacc[8][4];
        #pragma unroll
        for (int j = 0; j < 8; j++)
            #pragma unroll
            for (int i = 0; i < 4; i++) sacc[j][i] = 0.f;

        #pragma unroll
        for (int kk = 0; kk < 4; kk++) {
            #pragma unroll
            for (int j = 0; j < 8; j++) {
                uint32_t kb[2];
                ldsm_x2(kb, ksb + (uint32_t)(j*(8*SH2*4) + kk*32));
                mma_f16(sacc[j], qf[kk], kb[0], kb[1]);
            }
        }

        // ---- fixed-base softmax (pre-scaled) + mask*diag, P in registers ----
        const float* mp0 = msk + (m0 + lq)*MS + 2*lr;
        const float* mp1 = mp0 + 8*MS;
        #pragma unroll
        for (int j = 0; j < 8; j++) {
            float2 mk0 = *(const float2*)(mp0 + j*8);
            float2 mk1 = *(const float2*)(mp1 + j*8);
            float2 d2  = *(const float2*)(dsp + j*8 + 2*lr);
            float p0 = fast_ex2(sacc[j][0]);
            float p1 = fast_ex2(sacc[j][1]);
            float p2 = fast_ex2(sacc[j][2]);
            float p3 = fast_ex2(sacc[j][3]);
            lsum0 += p0 + p1;
            lsum1 += p2 + p3;
            sacc[j][0] = p0 * mk0.x * d2.x;
            sacc[j][1] = p1 * mk0.y * d2.y;
            sacc[j][2] = p2 * mk1.x * d2.x;
            sacc[j][3] = p3 * mk1.y * d2.y;
        }

        // ---- O += P @ V  (A-frags packed directly from C-frags of S) ----
        #pragma unroll
        for (int kk = 0; kk < 4; kk++) {
            uint32_t pa[4];
            pa[0] = f2h2(sacc[2*kk][0],   sacc[2*kk][1]);
            pa[1] = f2h2(sacc[2*kk][2],   sacc[2*kk][3]);
            pa[2] = f2h2(sacc[2*kk+1][0], sacc[2*kk+1][1]);
            pa[3] = f2h2(sacc[2*kk+1][2], sacc[2*kk+1][3]);
            #pragma unroll
            for (int jp = 0; jp < 4; jp++) {
                uint32_t vb[4];
                ldsm_x4_t(vb, vsb + (uint32_t)kk*(16*SH2*4) + (uint32_t)jp*32);
                mma_f16(oacc[2*jp],     pa, vb[0], vb[1]);
                mma_f16(oacc[2*jp + 1], pa, vb[2], vb[3]);
            }
        }
    }

    // ---- final l reduction over the quad and store ----
    lsum0 += __shfl_xor_sync(0xffffffffu, lsum0, 1);
    lsum0 += __shfl_xor_sync(0xffffffffu, lsum0, 2);
    lsum1 += __shfl_xor_sync(0xffffffffu, lsum1, 1);
    lsum1 += __shfl_xor_sync(0xffffffffu, lsum1, 2);
    float inv0 = 1.f / lsum0;
    float inv1 = 1.f / lsum1;

    const int r0 = q0 + m0 + lq;
    const int r1 = r0 + 8;
    #pragma unroll
    for (int j = 0; j < 8; j++) {
        int c = h*HD_ + j*8 + 2*lr;
        float2 o0; o0.x = oacc[j][0]*inv0; o0.y = oacc[j][1]*inv0;
        float2 o1; o1.x = oacc[j][2]*inv1; o1.y = oacc[j][3]*inv1;
        *(float2*)(out + ((size_t)b*NQ_ + r0)*DM_ + c) = o0;
        *(float2*)(out + ((size_t)b*NQ_ + r1)*DM_ + c) = o1;
    }
}

// ---------------------------------------------------------------------------
extern "C" void kernel_launch(void* const* d_in, const int* in_sizes, int n_in,
                              void* d_out, int out_size)
{
    const float* q       = (const float*)d_in[0];
    const float* k       = (const float*)d_in[1];
    const float* v       = (const float*)d_in[2];
    const float* mask    = (const float*)d_in[3];
    const float* pearson = (const float*)d_in[4];
    const float* Wq      = (const float*)d_in[5];
    const float* bq      = (const float*)d_in[6];
    const float* Wk      = (const float*)d_in[7];
    const float* bk      = (const float*)d_in[8];
    const float* Wv      = (const float*)d_in[9];
    const float* bv      = (const float*)d_in[10];
    float* out = (float*)d_out;

    cudaFuncSetAttribute(proj_kernel,
                         cudaFuncAttributeMaxDynamicSharedMemorySize, PROJ_SMEM);
    cudaFuncSetAttribute(attn_kernel,
                         cudaFuncAttributeMaxDynamicSharedMemorySize, ATTN_SMEM);

    prep_kernel<<<896, 256>>>(Wq, Wk, Wv, pearson);

    dim3 pg(DM_/128, (B_*NQ_)/128, 3);
    proj_kernel<<<pg, 512, PROJ_SMEM>>>(q, k, v, bq, bk, bv);

    dim3 ag(NQ_/128, H_, B_);
    attn_kernel<<<ag, 256, ATTN_SMEM>>>(mask, out);
}